// round 16
// baseline (speedup 1.0000x reference)
#include <cuda_runtime.h>
#include <cuda_fp16.h>
#include <math.h>
#include <stdint.h>

#define NSEG 8192
#define HDIM 512
#define MAXE 262144

// ---------------- device scratch ----------------
__device__ __half g_xlh[NSEG * HDIM];
__device__ float  g_xr[NSEG * HDIM];
__device__ float  g_buf0[NSEG * HDIM];
__device__ float  g_buf1[NSEG * HDIM];
__device__ __half g_xh[NSEG * HDIM];
__device__ __half g_wh[6 * HDIM * HDIM];
__device__ int    g_cnt[NSEG];
__device__ int    g_rowptr[NSEG + 1];
__device__ int    g_cursor[NSEG];
__device__ int    g_csrc[MAXE];

__device__ __forceinline__ uint32_t smem_u32(const void* p) {
    uint32_t a;
    asm("{ .reg .u64 t; cvta.to.shared.u64 t, %1; cvt.u32.u64 %0, t; }" : "=r"(a) : "l"(p));
    return a;
}
__device__ __forceinline__ void cp16(uint32_t dst, const void* src) {
    asm volatile("cp.async.cg.shared.global [%0], [%1], 16;" :: "r"(dst), "l"(src));
}
__device__ __forceinline__ uint32_t pack_h2(float lo, float hi) {
    uint32_t d;
    asm("cvt.rn.f16x2.f32 %0, %1, %2;" : "=r"(d) : "f"(hi), "f"(lo));
    return d;
}

// ---------------- launch 1: conversions (weights + input) + CSR histogram ----------------
__global__ void conv_hist_kernel(const float4* __restrict__ w0, const float4* __restrict__ w1,
                                 const float4* __restrict__ w2, const float4* __restrict__ w3,
                                 const float4* __restrict__ w4, const float4* __restrict__ w5,
                                 uint2* __restrict__ wh_out,
                                 const float4* __restrict__ xin, uint2* __restrict__ xh_out,
                                 const int* __restrict__ dst, int* __restrict__ cnt, int E)
{
    const int blk = blockIdx.x;
    if (blk < 1536) {
        const float4* ws[6] = { w0, w1, w2, w3, w4, w5 };
        const int m = blk >> 8;
        const int i = (blk & 255) * 256 + threadIdx.x;
        float4 v = ws[m][i];
        wh_out[(size_t)m * (HDIM * HDIM / 4) + i] = make_uint2(pack_h2(v.x, v.y), pack_h2(v.z, v.w));
    } else if (blk < 5632) {
        const int i = (blk - 1536) * 256 + threadIdx.x;
        float4 v = xin[i];
        xh_out[i] = make_uint2(pack_h2(v.x, v.y), pack_h2(v.z, v.w));
    } else {
        const int k = (blk - 5632) * 256 + threadIdx.x;
        if (k < E) atomicAdd(&cnt[dst[k]], 1);
    }
}

// ---------------- launch 2: CSR scan (self-resets cnt) ----------------
__global__ void scan_kernel(int* __restrict__ cnt, int* __restrict__ rowptr,
                            int* __restrict__ cursor)
{
    __shared__ int sums[256];
    const int tid = threadIdx.x;
    const int base = tid * 32;
    int local[32];
    int s = 0;
#pragma unroll
    for (int j = 0; j < 32; j++) {
        local[j] = s; s += cnt[base + j];
        cnt[base + j] = 0;
    }
    sums[tid] = s;
    __syncthreads();
    for (int off = 1; off < 256; off <<= 1) {
        int v = (tid >= off) ? sums[tid - off] : 0;
        __syncthreads();
        sums[tid] += v;
        __syncthreads();
    }
    const int excl = (tid == 0) ? 0 : sums[tid - 1];
#pragma unroll
    for (int j = 0; j < 32; j++) {
        int v = excl + local[j];
        rowptr[base + j] = v;
        cursor[base + j] = v;
    }
    if (tid == 255) rowptr[NSEG] = sums[255];
}

// ---------------- launch 3: scatter ----------------
__global__ void scatter_kernel(const int* __restrict__ src, const int* __restrict__ dst,
                               int* __restrict__ cursor, int* __restrict__ csrc, int E)
{
    int k = blockIdx.x * blockDim.x + threadIdx.x;
    if (k < E) {
        int p = atomicAdd(&cursor[dst[k]], 1);
        csrc[p] = src[k];
    }
}

// ============ GEMM v9: whole-tile fragment burst (16 LDSM then 64 HMMA) ============
#define A_STGH 5120
#define B_STGH 8448
#define STG_H  (A_STGH + B_STGH)
#define SMEM_GEMM_BYTES (3 * STG_H * 2)

__global__ __launch_bounds__(256, 1)
void gemm_tc9(const __half* __restrict__ Xh,
              const __half* __restrict__ Wh0, const float* __restrict__ b0, __half* __restrict__ Yh0,
              const __half* __restrict__ Wh1, const float* __restrict__ b1, float* __restrict__ Y1)
{
    const int bx = blockIdx.x;
    const int tid = threadIdx.x;

    const int bz  = bx >> 7;
    const int rem = bx & 127;
    const int rowBase = (rem >> 1) * 128;
    const int colBase = (rem & 1) * 256;

    const __half* W   = bz ? Wh1 : Wh0;
    const float* bias = bz ? b1 : b0;

    extern __shared__ __half sh[];
    const uint32_t smb = smem_u32(sh);

    const int warp = tid >> 5;
    const int lane = tid & 31;
    const int warpR = warp & 1;
    const int warpC = warp >> 1;
    const int qr = lane >> 2;
    const int qc = lane & 3;

    float acc[4][8][4];
#pragma unroll
    for (int i = 0; i < 4; i++)
#pragma unroll
        for (int j = 0; j < 8; j++)
#pragma unroll
            for (int r = 0; r < 4; r++) acc[i][j][r] = 0.f;

    auto issue = [&](int t) {
        const int s = t % 3;
        const int k0g = t * 32;
        const uint32_t aBase = smb + (uint32_t)(s * STG_H) * 2;
        const uint32_t bBase = aBase + (uint32_t)A_STGH * 2;
#pragma unroll
        for (int i = 0; i < 2; i++) {
            const int idx = tid + 256 * i;
            const int r  = idx >> 2;
            const int c8 = (idx & 3) * 8;
            cp16(aBase + (uint32_t)(r * 40 + c8) * 2,
                 Xh + (size_t)(rowBase + r) * 512 + k0g + c8);
        }
#pragma unroll
        for (int i = 0; i < 4; i++) {
            const int idx = tid + 256 * i;
            const int r  = idx >> 5;
            const int c8 = (idx & 31) * 8;
            cp16(bBase + (uint32_t)(r * 264 + c8) * 2,
                 W + (size_t)(k0g + r) * 512 + colBase + c8);
        }
        asm volatile("cp.async.commit_group;" ::: "memory");
    };

    issue(0);
    issue(1);

    for (int t = 0; t < 16; t++) {
        if (t < 15) {
            asm volatile("cp.async.wait_group 1;" ::: "memory");
        } else {
            asm volatile("cp.async.wait_group 0;" ::: "memory");
        }
        __syncthreads();

        const int s = t % 3;
        const uint32_t aS = smb + (uint32_t)(s * STG_H) * 2;
        const uint32_t bS = aS + (uint32_t)A_STGH * 2;

        // ---- fragment burst: 16 LDSM for both k-slabs ----
        uint32_t a[2][4][4], b[2][4][4];
#pragma unroll
        for (int ks = 0; ks < 2; ks++) {
            const int k0 = ks * 16;
#pragma unroll
            for (int mt = 0; mt < 4; mt++) {
                const int m0 = warpR * 64 + mt * 16;
                const int row = m0 + (lane & 15);
                const int col = k0 + (lane >> 4) * 8;
                const uint32_t addr = aS + (uint32_t)(row * 40 + col) * 2;
                asm volatile("ldmatrix.sync.aligned.m8n8.x4.shared.b16 {%0,%1,%2,%3}, [%4];"
                             : "=r"(a[ks][mt][0]), "=r"(a[ks][mt][1]),
                               "=r"(a[ks][mt][2]), "=r"(a[ks][mt][3])
                             : "r"(addr));
            }
#pragma unroll
            for (int np = 0; np < 4; np++) {
                const int n0 = warpC * 64 + np * 16;
                const int row = k0 + (lane & 7) + ((lane >> 3) & 1) * 8;
                const int col = n0 + (lane >> 4) * 8;
                const uint32_t addr = bS + (uint32_t)(row * 264 + col) * 2;
                asm volatile("ldmatrix.sync.aligned.m8n8.x4.trans.shared.b16 {%0,%1,%2,%3}, [%4];"
                             : "=r"(b[ks][np][0]), "=r"(b[ks][np][1]),
                               "=r"(b[ks][np][2]), "=r"(b[ks][np][3])
                             : "r"(addr));
            }
        }
        // ---- 64 HMMA ----
#pragma unroll
        for (int ks = 0; ks < 2; ks++)
#pragma unroll
            for (int mt = 0; mt < 4; mt++)
#pragma unroll
                for (int nt = 0; nt < 8; nt++) {
                    const uint32_t bb0 = b[ks][nt >> 1][(nt & 1) * 2 + 0];
                    const uint32_t bb1 = b[ks][nt >> 1][(nt & 1) * 2 + 1];
                    asm volatile(
                        "mma.sync.aligned.m16n8k16.row.col.f32.f16.f16.f32 "
                        "{%0,%1,%2,%3}, {%4,%5,%6,%7}, {%8,%9}, {%0,%1,%2,%3};"
                        : "+f"(acc[mt][nt][0]), "+f"(acc[mt][nt][1]),
                          "+f"(acc[mt][nt][2]), "+f"(acc[mt][nt][3])
                        : "r"(a[ks][mt][0]), "r"(a[ks][mt][1]),
                          "r"(a[ks][mt][2]), "r"(a[ks][mt][3]),
                          "r"(bb0), "r"(bb1));
                }
        if (t + 2 < 16) issue(t + 2);
    }

    if (bz == 0) {
#pragma unroll
        for (int mt = 0; mt < 4; mt++) {
#pragma unroll
            for (int nt = 0; nt < 8; nt++) {
                const int col = colBase + warpC * 64 + nt * 8 + qc * 2;
                const float bx2 = bias[col], by2 = bias[col + 1];
                const int r0 = rowBase + warpR * 64 + mt * 16 + qr;
                *(uint32_t*)(Yh0 + (size_t)r0 * 512 + col) =
                    pack_h2(acc[mt][nt][0] + bx2, acc[mt][nt][1] + by2);
                *(uint32_t*)(Yh0 + (size_t)(r0 + 8) * 512 + col) =
                    pack_h2(acc[mt][nt][2] + bx2, acc[mt][nt][3] + by2);
            }
        }
    } else {
#pragma unroll
        for (int mt = 0; mt < 4; mt++) {
#pragma unroll
            for (int nt = 0; nt < 8; nt++) {
                const int col = colBase + warpC * 64 + nt * 8 + qc * 2;
                const float bx2 = bias[col], by2 = bias[col + 1];
                const int r0 = rowBase + warpR * 64 + mt * 16 + qr;
                *(float2*)(Y1 + (size_t)r0 * 512 + col) =
                    make_float2(acc[mt][nt][0] + bx2, acc[mt][nt][1] + by2);
                *(float2*)(Y1 + (size_t)(r0 + 8) * 512 + col) =
                    make_float2(acc[mt][nt][2] + bx2, acc[mt][nt][3] + by2);
            }
        }
    }
}

// ============ fused edge3 (proven best, verbatim from r13) ============
__device__ __forceinline__ float lrelu(float v) { return v > 0.f ? v : 0.2f * v; }

__global__ __launch_bounds__(128)
void fused_edge3(const __half* __restrict__ xlh, const float* __restrict__ xr,
                 const float* __restrict__ a,
                 const int* __restrict__ rowptr, const int* __restrict__ csrc,
                 const float* __restrict__ bias,
                 float* __restrict__ out, __half* __restrict__ outh)
{
    __shared__ float s_xr[HDIM];
    __shared__ float s_a[HDIM];
    __shared__ float s_m[4], s_s[4];
    __shared__ float s_acc[4][HDIM];

    const int node = blockIdx.x;
    const int tid  = threadIdx.x;
    const int warp = tid >> 5;
    const int lane = tid & 31;

    ((float4*)s_xr)[tid] = ((const float4*)(xr + (size_t)node * HDIM))[tid];
    ((float4*)s_a)[tid]  = ((const float4*)a)[tid];
    __syncthreads();

    float4 xrv[4], av[4];
#pragma unroll
    for (int c = 0; c < 2; c++)
#pragma unroll
        for (int j = 0; j < 2; j++) {
            xrv[2 * c + j] = ((const float4*)s_xr)[2 * (c * 32 + lane) + j];
            av[2 * c + j]  = ((const float4*)s_a)[2 * (c * 32 + lane) + j];
        }

    const int s0 = rowptr[node], s1 = rowptr[node + 1];
    float m = -INFINITY, ssum = 0.f;
    float4 accv[4];
#pragma unroll
    for (int c = 0; c < 4; c++) accv[c] = make_float4(0.f, 0.f, 0.f, 0.f);

    for (int j = s0 + warp; j < s1; j += 8) {
        const int  j2   = j + 4;
        const bool has2 = (j2 < s1);
        const int sj0 = csrc[j];
        const int sj1 = has2 ? csrc[j2] : sj0;
        const uint4* r0 = (const uint4*)(xlh + (size_t)sj0 * HDIM);
        const uint4* r1 = (const uint4*)(xlh + (size_t)sj1 * HDIM);
        uint4 u0a = r0[lane], u0b = r0[32 + lane];
        uint4 u1a = r1[lane], u1b = r1[32 + lane];

        float4 v0[4], v1[4];
        {
            const __half2* h = (const __half2*)&u0a;
            float2 p0 = __half22float2(h[0]), p1 = __half22float2(h[1]);
            float2 p2 = __half22float2(h[2]), p3 = __half22float2(h[3]);
            v0[0] = make_float4(p0.x, p0.y, p1.x, p1.y);
            v0[1] = make_float4(p2.x, p2.y, p3.x, p3.y);
            h = (const __half2*)&u0b;
            p0 = __half22float2(h[0]); p1 = __half22float2(h[1]);
            p2 = __half22float2(h[2]); p3 = __half22float2(h[3]);
            v0[2] = make_float4(p0.x, p0.y, p1.x, p1.y);
            v0[3] = make_float4(p2.x, p2.y, p3.x, p3.y);
            h = (const __half2*)&u1a;
            p0 = __half22float2(h[0]); p1 = __half22float2(h[1]);
            p2 = __half22float2(h[2]); p3 = __half22float2(h[3]);
            v1[0] = make_float4(p0.x, p0.y, p1.x, p1.y);
            v1[1] = make_float4(p2.x, p2.y, p3.x, p3.y);
            h = (const __half2*)&u1b;
            p0 = __half22float2(h[0]); p1 = __half22float2(h[1]);
            p2 = __half22float2(h[2]); p3 = __half22float2(h[3]);
            v1[2] = make_float4(p0.x, p0.y, p1.x, p1.y);
            v1[3] = make_float4(p2.x, p2.y, p3.x, p3.y);
        }

        float p0 = 0.f, p1 = 0.f;
#pragma unroll
        for (int c = 0; c < 4; c++) {
            p0 = fmaf(av[c].x, lrelu(v0[c].x + xrv[c].x), p0);
            p0 = fmaf(av[c].y, lrelu(v0[c].y + xrv[c].y), p0);
            p0 = fmaf(av[c].z, lrelu(v0[c].z + xrv[c].z), p0);
            p0 = fmaf(av[c].w, lrelu(v0[c].w + xrv[c].w), p0);
            p1 = fmaf(av[c].x, lrelu(v1[c].x + xrv[c].x), p1);
            p1 = fmaf(av[c].y, lrelu(v1[c].y + xrv[c].y), p1);
            p1 = fmaf(av[c].z, lrelu(v1[c].z + xrv[c].z), p1);
            p1 = fmaf(av[c].w, lrelu(v1[c].w + xrv[c].w), p1);
        }
#pragma unroll
        for (int off = 16; off; off >>= 1) {
            p0 += __shfl_xor_sync(0xFFFFFFFFu, p0, off);
            p1 += __shfl_xor_sync(0xFFFFFFFFu, p1, off);
        }

        const float p1e = has2 ? p1 : -INFINITY;
        const float mn = fmaxf(m, fmaxf(p0, p1e));
        const float rs = __expf(m - mn);
        const float w0 = __expf(p0 - mn);
        const float w1 = has2 ? __expf(p1 - mn) : 0.f;
        ssum = ssum * rs + w0 + w1;
#pragma unroll
        for (int c = 0; c < 4; c++) {
            accv[c].x = fmaf(w1, v1[c].x, fmaf(w0, v0[c].x, accv[c].x * rs));
            accv[c].y = fmaf(w1, v1[c].y, fmaf(w0, v0[c].y, accv[c].y * rs));
            accv[c].z = fmaf(w1, v1[c].z, fmaf(w0, v0[c].z, accv[c].z * rs));
            accv[c].w = fmaf(w1, v1[c].w, fmaf(w0, v0[c].w, accv[c].w * rs));
        }
        m = mn;
    }

    if (lane == 0) { s_m[warp] = m; s_s[warp] = ssum; }
    __syncthreads();

    const float M = fmaxf(fmaxf(s_m[0], s_m[1]), fmaxf(s_m[2], s_m[3]));
    float S = 0.f;
#pragma unroll
    for (int w = 0; w < 4; w++)
        S += (s_m[w] == -INFINITY) ? 0.f : s_s[w] * __expf(s_m[w] - M);
    const float scale = (m == -INFINITY) ? 0.f : __expf(m - M);

#pragma unroll
    for (int c = 0; c < 2; c++)
#pragma unroll
        for (int j = 0; j < 2; j++) {
            float4 t = accv[2 * c + j];
            t.x *= scale; t.y *= scale; t.z *= scale; t.w *= scale;
            ((float4*)s_acc[warp])[2 * (c * 32 + lane) + j] = t;
        }
    __syncthreads();

    const float inv = (M == -INFINITY) ? 0.f : 1.f / S;
    float4 o = ((const float4*)bias)[tid];
    float4 q0 = ((const float4*)s_acc[0])[tid];
    float4 q1 = ((const float4*)s_acc[1])[tid];
    float4 q2 = ((const float4*)s_acc[2])[tid];
    float4 q3 = ((const float4*)s_acc[3])[tid];
    o.x += (q0.x + q1.x + q2.x + q3.x) * inv;
    o.y += (q0.y + q1.y + q2.y + q3.y) * inv;
    o.z += (q0.z + q1.z + q2.z + q3.z) * inv;
    o.w += (q0.w + q1.w + q2.w + q3.w) * inv;
    ((float4*)(out + (size_t)node * HDIM))[tid] = o;
    ((uint2*)(outh + (size_t)node * HDIM))[tid] =
        make_uint2(pack_h2(o.x, o.y), pack_h2(o.z, o.w));
}

// ---------------- launch: 9 kernels (gemm1 in profiled slot 4) ----------------
extern "C" void kernel_launch(void* const* d_in, const int* in_sizes, int n_in,
                              void* d_out, int out_size)
{
    const float* x0   = (const float*)d_in[0];
    const int*   eidx = (const int*)d_in[2];
    const int    E    = in_sizes[2] / 2;
    float*       out  = (float*)d_out;

    const int* src = eidx;
    const int* dst = eidx + E;

    float *xr, *b0, *b1;
    __half *xlh, *xh, *wh;
    int *cnt, *rowptr, *cursor, *csrc;
    cudaGetSymbolAddress((void**)&xlh,    g_xlh);
    cudaGetSymbolAddress((void**)&xr,     g_xr);
    cudaGetSymbolAddress((void**)&b0,     g_buf0);
    cudaGetSymbolAddress((void**)&b1,     g_buf1);
    cudaGetSymbolAddress((void**)&xh,     g_xh);
    cudaGetSymbolAddress((void**)&wh,     g_wh);
    cudaGetSymbolAddress((void**)&cnt,    g_cnt);
    cudaGetSymbolAddress((void**)&rowptr, g_rowptr);
    cudaGetSymbolAddress((void**)&cursor, g_cursor);
    cudaGetSymbolAddress((void**)&csrc,   g_csrc);

    cudaFuncSetAttribute(gemm_tc9, cudaFuncAttributeMaxDynamicSharedMemorySize, SMEM_GEMM_BYTES);

    // 1: conversions + histogram
    conv_hist_kernel<<<5632 + (E + 255) / 256, 256>>>(
        (const float4*)d_in[3], (const float4*)d_in[5],
        (const float4*)d_in[9], (const float4*)d_in[11],
        (const float4*)d_in[15], (const float4*)d_in[17],
        (uint2*)wh, (const float4*)x0, (uint2*)xh,
        dst, cnt, E);
    // 2: scan
    scan_kernel<<<1, 256>>>(cnt, rowptr, cursor);
    // 3: scatter
    scatter_kernel<<<(E + 255) / 256, 256>>>(src, dst, cursor, csrc, E);

    float* outs[3] = { b0, b1, out };
    for (int L = 0; L < 3; L++) {
        const int base = 3 + 6 * L;
        const float* bl   = (const float*)d_in[base + 1];
        const float* br   = (const float*)d_in[base + 3];
        const float* avec = (const float*)d_in[base + 4];
        const float* bias = (const float*)d_in[base + 5];
        const __half* whl = wh + (size_t)(2 * L)     * HDIM * HDIM;
        const __half* whr = wh + (size_t)(2 * L + 1) * HDIM * HDIM;

        // launch 4 (L=0) = gemm1 -> profiled slot
        gemm_tc9<<<256, 256, SMEM_GEMM_BYTES>>>(xh, whl, bl, xlh, whr, br, xr);
        fused_edge3<<<NSEG, 128>>>(xlh, xr, avec, rowptr, csrc, bias, outs[L], xh);
    }
}

// round 17
// speedup vs baseline: 1.0760x; 1.0760x over previous
#include <cuda_runtime.h>
#include <cuda_fp16.h>
#include <math.h>
#include <stdint.h>

#define NSEG 8192
#define HDIM 512
#define MAXE 262144

// ---------------- device scratch ----------------
__device__ __half g_xlh[NSEG * HDIM];
__device__ float  g_xr[NSEG * HDIM];
__device__ float  g_buf0[NSEG * HDIM];
__device__ __half g_xh[NSEG * HDIM];
__device__ __half g_wh[6 * HDIM * HDIM];
__device__ int    g_cnt[NSEG];
__device__ int    g_rowptr[NSEG + 1];
__device__ int    g_cursor[NSEG];
__device__ int    g_csrc[MAXE];

__device__ __forceinline__ uint32_t smem_u32(const void* p) {
    uint32_t a;
    asm("{ .reg .u64 t; cvta.to.shared.u64 t, %1; cvt.u32.u64 %0, t; }" : "=r"(a) : "l"(p));
    return a;
}
__device__ __forceinline__ void cp16(uint32_t dst, const void* src) {
    asm volatile("cp.async.cg.shared.global [%0], [%1], 16;" :: "r"(dst), "l"(src));
}
__device__ __forceinline__ uint32_t pack_h2(float lo, float hi) {
    uint32_t d;
    asm("cvt.rn.f16x2.f32 %0, %1, %2;" : "=r"(d) : "f"(hi), "f"(lo));
    return d;
}

// ---------------- launch 1: conversions (weights + input) + CSR histogram ----------------
__global__ void conv_hist_kernel(const float4* __restrict__ w0, const float4* __restrict__ w1,
                                 const float4* __restrict__ w2, const float4* __restrict__ w3,
                                 const float4* __restrict__ w4, const float4* __restrict__ w5,
                                 uint2* __restrict__ wh_out,
                                 const float4* __restrict__ xin, uint2* __restrict__ xh_out,
                                 const int* __restrict__ dst, int* __restrict__ cnt, int E)
{
    const int blk = blockIdx.x;
    if (blk < 1536) {
        const float4* ws[6] = { w0, w1, w2, w3, w4, w5 };
        const int m = blk >> 8;
        const int i = (blk & 255) * 256 + threadIdx.x;
        float4 v = ws[m][i];
        wh_out[(size_t)m * (HDIM * HDIM / 4) + i] = make_uint2(pack_h2(v.x, v.y), pack_h2(v.z, v.w));
    } else if (blk < 5632) {
        const int i = (blk - 1536) * 256 + threadIdx.x;
        float4 v = xin[i];
        xh_out[i] = make_uint2(pack_h2(v.x, v.y), pack_h2(v.z, v.w));
    } else {
        const int k = (blk - 5632) * 256 + threadIdx.x;
        if (k < E) atomicAdd(&cnt[dst[k]], 1);
    }
}

// ============ GEMM (proven config) + optional fused scan block (r13 layout) ============
#define A_STGH 5120
#define B_STGH 8448
#define STG_H  (A_STGH + B_STGH)
#define SMEM_GEMM_BYTES (3 * STG_H * 2)

__global__ __launch_bounds__(256, 1)
void gemm_tc8(const __half* __restrict__ Xh,
              const __half* __restrict__ Wh0, const float* __restrict__ b0, __half* __restrict__ Yh0,
              const __half* __restrict__ Wh1, const float* __restrict__ b1, float* __restrict__ Y1,
              int* __restrict__ cnt, int* __restrict__ rowptr, int* __restrict__ cursor)
{
    const int bx = blockIdx.x;
    const int tid  = threadIdx.x;

    if (bx >= 256) {
        __shared__ int sums[256];
        const int base = tid * 32;
        int local[32];
        int s = 0;
#pragma unroll
        for (int j = 0; j < 32; j++) {
            local[j] = s; s += cnt[base + j];
            cnt[base + j] = 0;
        }
        sums[tid] = s;
        __syncthreads();
        for (int off = 1; off < 256; off <<= 1) {
            int v = (tid >= off) ? sums[tid - off] : 0;
            __syncthreads();
            sums[tid] += v;
            __syncthreads();
        }
        const int excl = (tid == 0) ? 0 : sums[tid - 1];
#pragma unroll
        for (int j = 0; j < 32; j++) {
            int v = excl + local[j];
            rowptr[base + j] = v;
            cursor[base + j] = v;
        }
        if (tid == 255) rowptr[NSEG] = sums[255];
        return;
    }

    const int bz  = bx >> 7;
    const int rem = bx & 127;
    const int rowBase = (rem >> 1) * 128;
    const int colBase = (rem & 1) * 256;

    const __half* W   = bz ? Wh1 : Wh0;
    const float* bias = bz ? b1 : b0;

    extern __shared__ __half sh[];
    const uint32_t smb = smem_u32(sh);

    const int warp = tid >> 5;
    const int lane = tid & 31;
    const int warpR = warp & 1;
    const int warpC = warp >> 1;
    const int qr = lane >> 2;
    const int qc = lane & 3;

    float acc[4][8][4];
#pragma unroll
    for (int i = 0; i < 4; i++)
#pragma unroll
        for (int j = 0; j < 8; j++)
#pragma unroll
            for (int r = 0; r < 4; r++) acc[i][j][r] = 0.f;

    auto issue = [&](int t) {
        const int s = t % 3;
        const int k0g = t * 32;
        const uint32_t aBase = smb + (uint32_t)(s * STG_H) * 2;
        const uint32_t bBase = aBase + (uint32_t)A_STGH * 2;
#pragma unroll
        for (int i = 0; i < 2; i++) {
            const int idx = tid + 256 * i;
            const int r  = idx >> 2;
            const int c8 = (idx & 3) * 8;
            cp16(aBase + (uint32_t)(r * 40 + c8) * 2,
                 Xh + (size_t)(rowBase + r) * 512 + k0g + c8);
        }
#pragma unroll
        for (int i = 0; i < 4; i++) {
            const int idx = tid + 256 * i;
            const int r  = idx >> 5;
            const int c8 = (idx & 31) * 8;
            cp16(bBase + (uint32_t)(r * 264 + c8) * 2,
                 W + (size_t)(k0g + r) * 512 + colBase + c8);
        }
        asm volatile("cp.async.commit_group;" ::: "memory");
    };

    issue(0);
    issue(1);

    for (int t = 0; t < 16; t++) {
        if (t < 15) {
            asm volatile("cp.async.wait_group 1;" ::: "memory");
        } else {
            asm volatile("cp.async.wait_group 0;" ::: "memory");
        }
        __syncthreads();

        const int s = t % 3;
        const uint32_t aS = smb + (uint32_t)(s * STG_H) * 2;
        const uint32_t bS = aS + (uint32_t)A_STGH * 2;

#pragma unroll
        for (int ks = 0; ks < 2; ks++) {
            const int k0 = ks * 16;
            uint32_t a[4][4], b[4][4];
#pragma unroll
            for (int mt = 0; mt < 4; mt++) {
                const int m0 = warpR * 64 + mt * 16;
                const int row = m0 + (lane & 15);
                const int col = k0 + (lane >> 4) * 8;
                const uint32_t addr = aS + (uint32_t)(row * 40 + col) * 2;
                asm volatile("ldmatrix.sync.aligned.m8n8.x4.shared.b16 {%0,%1,%2,%3}, [%4];"
                             : "=r"(a[mt][0]), "=r"(a[mt][1]), "=r"(a[mt][2]), "=r"(a[mt][3])
                             : "r"(addr));
            }
#pragma unroll
            for (int np = 0; np < 4; np++) {
                const int n0 = warpC * 64 + np * 16;
                const int row = k0 + (lane & 7) + ((lane >> 3) & 1) * 8;
                const int col = n0 + (lane >> 4) * 8;
                const uint32_t addr = bS + (uint32_t)(row * 264 + col) * 2;
                asm volatile("ldmatrix.sync.aligned.m8n8.x4.trans.shared.b16 {%0,%1,%2,%3}, [%4];"
                             : "=r"(b[np][0]), "=r"(b[np][1]), "=r"(b[np][2]), "=r"(b[np][3])
                             : "r"(addr));
            }
#pragma unroll
            for (int mt = 0; mt < 4; mt++)
#pragma unroll
                for (int nt = 0; nt < 8; nt++) {
                    const uint32_t bb0 = b[nt >> 1][(nt & 1) * 2 + 0];
                    const uint32_t bb1 = b[nt >> 1][(nt & 1) * 2 + 1];
                    asm volatile(
                        "mma.sync.aligned.m16n8k16.row.col.f32.f16.f16.f32 "
                        "{%0,%1,%2,%3}, {%4,%5,%6,%7}, {%8,%9}, {%0,%1,%2,%3};"
                        : "+f"(acc[mt][nt][0]), "+f"(acc[mt][nt][1]),
                          "+f"(acc[mt][nt][2]), "+f"(acc[mt][nt][3])
                        : "r"(a[mt][0]), "r"(a[mt][1]), "r"(a[mt][2]), "r"(a[mt][3]),
                          "r"(bb0), "r"(bb1));
                }
        }
        if (t + 2 < 16) issue(t + 2);
    }

    if (bz == 0) {
#pragma unroll
        for (int mt = 0; mt < 4; mt++) {
#pragma unroll
            for (int nt = 0; nt < 8; nt++) {
                const int col = colBase + warpC * 64 + nt * 8 + qc * 2;
                const float bx2 = bias[col], by2 = bias[col + 1];
                const int r0 = rowBase + warpR * 64 + mt * 16 + qr;
                *(uint32_t*)(Yh0 + (size_t)r0 * 512 + col) =
                    pack_h2(acc[mt][nt][0] + bx2, acc[mt][nt][1] + by2);
                *(uint32_t*)(Yh0 + (size_t)(r0 + 8) * 512 + col) =
                    pack_h2(acc[mt][nt][2] + bx2, acc[mt][nt][3] + by2);
            }
        }
    } else {
#pragma unroll
        for (int mt = 0; mt < 4; mt++) {
#pragma unroll
            for (int nt = 0; nt < 8; nt++) {
                const int col = colBase + warpC * 64 + nt * 8 + qc * 2;
                const float bx2 = bias[col], by2 = bias[col + 1];
                const int r0 = rowBase + warpR * 64 + mt * 16 + qr;
                *(float2*)(Y1 + (size_t)r0 * 512 + col) =
                    make_float2(acc[mt][nt][0] + bx2, acc[mt][nt][1] + by2);
                *(float2*)(Y1 + (size_t)(r0 + 8) * 512 + col) =
                    make_float2(acc[mt][nt][2] + bx2, acc[mt][nt][3] + by2);
            }
        }
    }
}

// ---------------- scatter ----------------
__global__ void scatter_kernel(const int* __restrict__ src, const int* __restrict__ dst,
                               int* __restrict__ cursor, int* __restrict__ csrc, int E)
{
    int k = blockIdx.x * blockDim.x + threadIdx.x;
    if (k < E) {
        int p = atomicAdd(&cursor[dst[k]], 1);
        csrc[p] = src[k];
    }
}

// ============ fused edge3 (proven best) + dead-store elimination flags ============
__device__ __forceinline__ float lrelu(float v) { return v > 0.f ? v : 0.2f * v; }

__global__ __launch_bounds__(128)
void fused_edge3(const __half* __restrict__ xlh, const float* __restrict__ xr,
                 const float* __restrict__ a,
                 const int* __restrict__ rowptr, const int* __restrict__ csrc,
                 const float* __restrict__ bias,
                 float* __restrict__ out, __half* __restrict__ outh,
                 int write_f32, int write_f16)
{
    __shared__ float s_xr[HDIM];
    __shared__ float s_a[HDIM];
    __shared__ float s_m[4], s_s[4];
    __shared__ float s_acc[4][HDIM];

    const int node = blockIdx.x;
    const int tid  = threadIdx.x;
    const int warp = tid >> 5;
    const int lane = tid & 31;

    ((float4*)s_xr)[tid] = ((const float4*)(xr + (size_t)node * HDIM))[tid];
    ((float4*)s_a)[tid]  = ((const float4*)a)[tid];
    __syncthreads();

    float4 xrv[4], av[4];
#pragma unroll
    for (int c = 0; c < 2; c++)
#pragma unroll
        for (int j = 0; j < 2; j++) {
            xrv[2 * c + j] = ((const float4*)s_xr)[2 * (c * 32 + lane) + j];
            av[2 * c + j]  = ((const float4*)s_a)[2 * (c * 32 + lane) + j];
        }

    const int s0 = rowptr[node], s1 = rowptr[node + 1];
    float m = -INFINITY, ssum = 0.f;
    float4 accv[4];
#pragma unroll
    for (int c = 0; c < 4; c++) accv[c] = make_float4(0.f, 0.f, 0.f, 0.f);

    for (int j = s0 + warp; j < s1; j += 8) {
        const int  j2   = j + 4;
        const bool has2 = (j2 < s1);
        const int sj0 = csrc[j];
        const int sj1 = has2 ? csrc[j2] : sj0;
        const uint4* r0 = (const uint4*)(xlh + (size_t)sj0 * HDIM);
        const uint4* r1 = (const uint4*)(xlh + (size_t)sj1 * HDIM);
        uint4 u0a = r0[lane], u0b = r0[32 + lane];
        uint4 u1a = r1[lane], u1b = r1[32 + lane];

        float4 v0[4], v1[4];
        {
            const __half2* h = (const __half2*)&u0a;
            float2 p0 = __half22float2(h[0]), p1 = __half22float2(h[1]);
            float2 p2 = __half22float2(h[2]), p3 = __half22float2(h[3]);
            v0[0] = make_float4(p0.x, p0.y, p1.x, p1.y);
            v0[1] = make_float4(p2.x, p2.y, p3.x, p3.y);
            h = (const __half2*)&u0b;
            p0 = __half22float2(h[0]); p1 = __half22float2(h[1]);
            p2 = __half22float2(h[2]); p3 = __half22float2(h[3]);
            v0[2] = make_float4(p0.x, p0.y, p1.x, p1.y);
            v0[3] = make_float4(p2.x, p2.y, p3.x, p3.y);
            h = (const __half2*)&u1a;
            p0 = __half22float2(h[0]); p1 = __half22float2(h[1]);
            p2 = __half22float2(h[2]); p3 = __half22float2(h[3]);
            v1[0] = make_float4(p0.x, p0.y, p1.x, p1.y);
            v1[1] = make_float4(p2.x, p2.y, p3.x, p3.y);
            h = (const __half2*)&u1b;
            p0 = __half22float2(h[0]); p1 = __half22float2(h[1]);
            p2 = __half22float2(h[2]); p3 = __half22float2(h[3]);
            v1[2] = make_float4(p0.x, p0.y, p1.x, p1.y);
            v1[3] = make_float4(p2.x, p2.y, p3.x, p3.y);
        }

        float p0 = 0.f, p1 = 0.f;
#pragma unroll
        for (int c = 0; c < 4; c++) {
            p0 = fmaf(av[c].x, lrelu(v0[c].x + xrv[c].x), p0);
            p0 = fmaf(av[c].y, lrelu(v0[c].y + xrv[c].y), p0);
            p0 = fmaf(av[c].z, lrelu(v0[c].z + xrv[c].z), p0);
            p0 = fmaf(av[c].w, lrelu(v0[c].w + xrv[c].w), p0);
            p1 = fmaf(av[c].x, lrelu(v1[c].x + xrv[c].x), p1);
            p1 = fmaf(av[c].y, lrelu(v1[c].y + xrv[c].y), p1);
            p1 = fmaf(av[c].z, lrelu(v1[c].z + xrv[c].z), p1);
            p1 = fmaf(av[c].w, lrelu(v1[c].w + xrv[c].w), p1);
        }
#pragma unroll
        for (int off = 16; off; off >>= 1) {
            p0 += __shfl_xor_sync(0xFFFFFFFFu, p0, off);
            p1 += __shfl_xor_sync(0xFFFFFFFFu, p1, off);
        }

        const float p1e = has2 ? p1 : -INFINITY;
        const float mn = fmaxf(m, fmaxf(p0, p1e));
        const float rs = __expf(m - mn);
        const float w0 = __expf(p0 - mn);
        const float w1 = has2 ? __expf(p1 - mn) : 0.f;
        ssum = ssum * rs + w0 + w1;
#pragma unroll
        for (int c = 0; c < 4; c++) {
            accv[c].x = fmaf(w1, v1[c].x, fmaf(w0, v0[c].x, accv[c].x * rs));
            accv[c].y = fmaf(w1, v1[c].y, fmaf(w0, v0[c].y, accv[c].y * rs));
            accv[c].z = fmaf(w1, v1[c].z, fmaf(w0, v0[c].z, accv[c].z * rs));
            accv[c].w = fmaf(w1, v1[c].w, fmaf(w0, v0[c].w, accv[c].w * rs));
        }
        m = mn;
    }

    if (lane == 0) { s_m[warp] = m; s_s[warp] = ssum; }
    __syncthreads();

    const float M = fmaxf(fmaxf(s_m[0], s_m[1]), fmaxf(s_m[2], s_m[3]));
    float S = 0.f;
#pragma unroll
    for (int w = 0; w < 4; w++)
        S += (s_m[w] == -INFINITY) ? 0.f : s_s[w] * __expf(s_m[w] - M);
    const float scale = (m == -INFINITY) ? 0.f : __expf(m - M);

#pragma unroll
    for (int c = 0; c < 2; c++)
#pragma unroll
        for (int j = 0; j < 2; j++) {
            float4 t = accv[2 * c + j];
            t.x *= scale; t.y *= scale; t.z *= scale; t.w *= scale;
            ((float4*)s_acc[warp])[2 * (c * 32 + lane) + j] = t;
        }
    __syncthreads();

    const float inv = (M == -INFINITY) ? 0.f : 1.f / S;
    float4 o = ((const float4*)bias)[tid];
    float4 q0 = ((const float4*)s_acc[0])[tid];
    float4 q1 = ((const float4*)s_acc[1])[tid];
    float4 q2 = ((const float4*)s_acc[2])[tid];
    float4 q3 = ((const float4*)s_acc[3])[tid];
    o.x += (q0.x + q1.x + q2.x + q3.x) * inv;
    o.y += (q0.y + q1.y + q2.y + q3.y) * inv;
    o.z += (q0.z + q1.z + q2.z + q3.z) * inv;
    o.w += (q0.w + q1.w + q2.w + q3.w) * inv;
    if (write_f32)
        ((float4*)(out + (size_t)node * HDIM))[tid] = o;
    if (write_f16)
        ((uint2*)(outh + (size_t)node * HDIM))[tid] =
            make_uint2(pack_h2(o.x, o.y), pack_h2(o.z, o.w));
}

// ---------------- launch: 8 kernels (r13 structure) ----------------
extern "C" void kernel_launch(void* const* d_in, const int* in_sizes, int n_in,
                              void* d_out, int out_size)
{
    const float* x0   = (const float*)d_in[0];
    const int*   eidx = (const int*)d_in[2];
    const int    E    = in_sizes[2] / 2;
    float*       out  = (float*)d_out;

    const int* src = eidx;
    const int* dst = eidx + E;

    float *xr, *b0;
    __half *xlh, *xh, *wh;
    int *cnt, *rowptr, *cursor, *csrc;
    cudaGetSymbolAddress((void**)&xlh,    g_xlh);
    cudaGetSymbolAddress((void**)&xr,     g_xr);
    cudaGetSymbolAddress((void**)&b0,     g_buf0);
    cudaGetSymbolAddress((void**)&xh,     g_xh);
    cudaGetSymbolAddress((void**)&wh,     g_wh);
    cudaGetSymbolAddress((void**)&cnt,    g_cnt);
    cudaGetSymbolAddress((void**)&rowptr, g_rowptr);
    cudaGetSymbolAddress((void**)&cursor, g_cursor);
    cudaGetSymbolAddress((void**)&csrc,   g_csrc);

    cudaFuncSetAttribute(gemm_tc8, cudaFuncAttributeMaxDynamicSharedMemorySize, SMEM_GEMM_BYTES);

    // 1: conversions + histogram
    conv_hist_kernel<<<5632 + (E + 255) / 256, 256>>>(
        (const float4*)d_in[3], (const float4*)d_in[5],
        (const float4*)d_in[9], (const float4*)d_in[11],
        (const float4*)d_in[15], (const float4*)d_in[17],
        (uint2*)wh, (const float4*)x0, (uint2*)xh,
        dst, cnt, E);

    // 2: gemm layer 1 + fused scan
    {
        const float* bl = (const float*)d_in[4];
        const float* br = (const float*)d_in[6];
        gemm_tc8<<<257, 256, SMEM_GEMM_BYTES>>>(xh, wh, bl, xlh,
                                                wh + (size_t)HDIM * HDIM, br, xr,
                                                cnt, rowptr, cursor);
    }
    // 3: scatter
    scatter_kernel<<<(E + 255) / 256, 256>>>(src, dst, cursor, csrc, E);

    for (int L = 0; L < 3; L++) {
        const int base = 3 + 6 * L;
        const float* avec = (const float*)d_in[base + 4];
        const float* bias = (const float*)d_in[base + 5];

        if (L > 0) {
            const float* bl = (const float*)d_in[base + 1];
            const float* br = (const float*)d_in[base + 3];
            const __half* whl = wh + (size_t)(2 * L)     * HDIM * HDIM;
            const __half* whr = wh + (size_t)(2 * L + 1) * HDIM * HDIM;
            gemm_tc8<<<256, 256, SMEM_GEMM_BYTES>>>(xh, whl, bl, xlh, whr, br, xr,
                                                    cnt, rowptr, cursor);
        }
        // fp32 out only needed for the final layer; fp16 xh only for layers 0,1
        float* outp = (L == 2) ? out : b0;
        fused_edge3<<<NSEG, 128>>>(xlh, xr, avec, rowptr, csrc, bias, outp, xh,
                                   (L == 2) ? 1 : 0, (L < 2) ? 1 : 0);
    }
}